// round 6
// baseline (speedup 1.0000x reference)
#include <cuda_runtime.h>
#include <cuda_bf16.h>
#include <math.h>

#define S 1024
#define B 128
#define E 10
#define H 256
#define L 4
#define G4 1024           // 4*H
#define NBPL 32           // blocks per layer
#define NBLK (NBPL * L)   // 128 persistent blocks
#define NW 4              // warps per block (m32 per warp)

// ---------------- device scratch (static; no allocations) ----------------
// weight fragments: [l][nb][kt][nt][lane] = uint4(whi.x, whi.y, wlo.x, wlo.y)
__device__ __align__(16) uint4  g_Wp[4 * 32 * 32 * 4 * 32];
__device__ float  g_bias[4 * 32 * 32];
__device__ float  g_w0p[32 * 32 * 10];
__device__ float  g_S[S * B * E];
__device__ float  g_C0[L * B * H];
// h state: [l][slot(3)][b][64 uint4]; unit u64 = (hi(j),hi(j+1),lo(j),lo(j+1))
__device__ __align__(16) uint4 g_Hq[L * 3 * B * 64];
__device__ int g_cnt[L * NW];   // per (layer, warp) completed-step counters (x32 blocks)

// ---------------- helpers ----------------
// perm-unit index for even col j: u64-unit within row
__device__ __host__ __forceinline__ int unitj(int j) {
    return (j >> 4) * 8 + (((j & 6) >> 1) << 1) + ((j >> 3) & 1);
}

__device__ __forceinline__ unsigned pk(__nv_bfloat16 a, __nv_bfloat16 b) {
    __nv_bfloat162 t; t.x = a; t.y = b;
    return *reinterpret_cast<unsigned*>(&t);
}

__device__ __forceinline__ void mma16816(float c[4], const unsigned a[4],
                                         unsigned b0, unsigned b1) {
    asm volatile(
        "mma.sync.aligned.m16n8k16.row.col.f32.bf16.bf16.f32 "
        "{%0,%1,%2,%3},{%4,%5,%6,%7},{%8,%9},{%0,%1,%2,%3};"
        : "+f"(c[0]), "+f"(c[1]), "+f"(c[2]), "+f"(c[3])
        : "r"(a[0]), "r"(a[1]), "r"(a[2]), "r"(a[3]), "r"(b0), "r"(b1));
}

__device__ __forceinline__ float fsig(float x) {
    return __fdividef(1.0f, 1.0f + __expf(-x));
}
__device__ __forceinline__ float ftanh(float x) {
    return 1.0f - __fdividef(2.0f, __expf(2.0f * x) + 1.0f);
}

__device__ __forceinline__ int ld_acq(const int* p) {
    int v;
    asm volatile("ld.acquire.gpu.global.b32 %0, [%1];" : "=r"(v) : "l"(p) : "memory");
    return v;
}
__device__ __forceinline__ void red_rel(int* p, int v) {
    asm volatile("red.release.gpu.global.add.s32 [%0], %1;" :: "l"(p), "r"(v) : "memory");
}

// one 16-kt half of the K sweep over TWO m16 fragments (m=32 per warp).
// Hq = per-lane activation ptr for frag0 (kt=0); frag1 rows at +16*64.
__device__ __forceinline__ void do_half(const uint4* __restrict__ Hq,
                                        const uint4* __restrict__ Wq,
                                        float acc[2][4][4]) {
#pragma unroll
    for (int kt = 0; kt < 16; ++kt) {
        uint4 u1a = __ldcg(Hq + kt * 4);
        uint4 u2a = __ldcg(Hq + kt * 4 + 8 * 64);
        uint4 u1b = __ldcg(Hq + kt * 4 + 16 * 64);
        uint4 u2b = __ldcg(Hq + kt * 4 + 24 * 64);
        unsigned a0[4]  = {u1a.x, u2a.x, u1a.z, u2a.z};
        unsigned a0l[4] = {u1a.y, u2a.y, u1a.w, u2a.w};
        unsigned a1[4]  = {u1b.x, u2b.x, u1b.z, u2b.z};
        unsigned a1l[4] = {u1b.y, u2b.y, u1b.w, u2b.w};
        uint4 w0 = Wq[kt * 128 + 0];
        uint4 w1 = Wq[kt * 128 + 32];
        uint4 w2 = Wq[kt * 128 + 64];
        uint4 w3 = Wq[kt * 128 + 96];
        // pass 1: Ahi * Whi (8 independent MMAs)
        mma16816(acc[0][0], a0, w0.x, w0.y);
        mma16816(acc[0][1], a0, w1.x, w1.y);
        mma16816(acc[0][2], a0, w2.x, w2.y);
        mma16816(acc[0][3], a0, w3.x, w3.y);
        mma16816(acc[1][0], a1, w0.x, w0.y);
        mma16816(acc[1][1], a1, w1.x, w1.y);
        mma16816(acc[1][2], a1, w2.x, w2.y);
        mma16816(acc[1][3], a1, w3.x, w3.y);
        // pass 2: Alo * Whi
        mma16816(acc[0][0], a0l, w0.x, w0.y);
        mma16816(acc[0][1], a0l, w1.x, w1.y);
        mma16816(acc[0][2], a0l, w2.x, w2.y);
        mma16816(acc[0][3], a0l, w3.x, w3.y);
        mma16816(acc[1][0], a1l, w0.x, w0.y);
        mma16816(acc[1][1], a1l, w1.x, w1.y);
        mma16816(acc[1][2], a1l, w2.x, w2.y);
        mma16816(acc[1][3], a1l, w3.x, w3.y);
        // pass 3: Ahi * Wlo
        mma16816(acc[0][0], a0, w0.z, w0.w);
        mma16816(acc[0][1], a0, w1.z, w1.w);
        mma16816(acc[0][2], a0, w2.z, w2.w);
        mma16816(acc[0][3], a0, w3.z, w3.w);
        mma16816(acc[1][0], a1, w0.z, w0.w);
        mma16816(acc[1][1], a1, w1.z, w1.w);
        mma16816(acc[1][2], a1, w2.z, w2.w);
        mma16816(acc[1][3], a1, w3.z, w3.w);
    }
}

// ---------------- prep 1: pack weights + biases + layer0 Wih ----------------
__global__ void k_prep(const float* __restrict__ Wih0, const float* __restrict__ Wihr,
                       const float* __restrict__ Whh,  const float* __restrict__ bih,
                       const float* __restrict__ bhh) {
    int idx = blockIdx.x * 256 + threadIdx.x;
    if (idx < 4 * 32 * 32 * 4 * 32) {
        int lane = idx & 31;
        int nt   = (idx >> 5) & 3;
        int kt   = (idx >> 7) & 31;
        int nb   = (idx >> 12) & 31;
        int l    = idx >> 17;
        if (l == 0 && kt >= 16) return;
        int ncol = lane >> 2;
        int r    = nt * 256 + nb * 8 + ncol;
        int k0   = kt * 16 + (lane & 3) * 2;
        __nv_bfloat16 hi[4], lo[4];
#pragma unroll
        for (int q = 0; q < 4; q++) {
            int k = k0 + (q >> 1) * 8 + (q & 1);   // k0,k0+1,k0+8,k0+9
            float w;
            if (l == 0)       w = Whh[(size_t)r * H + k];
            else if (k < H)   w = Wihr[(size_t)((l - 1) * G4 + r) * H + k];
            else              w = Whh[(size_t)(l * G4 + r) * H + (k - H)];
            hi[q] = __float2bfloat16(w);
            lo[q] = __float2bfloat16(w - __bfloat162float(hi[q]));
        }
        g_Wp[idx] = make_uint4(pk(hi[0], hi[1]), pk(hi[2], hi[3]),
                               pk(lo[0], lo[1]), pk(lo[2], lo[3]));
    } else {
        int j = idx - 4 * 32 * 32 * 4 * 32;
        if (j < 4096) {
            int l = j >> 10, nb = (j >> 5) & 31, nl = j & 31;
            int r = (nl >> 3) * 256 + nb * 8 + (nl & 7);
            g_bias[j] = bih[l * G4 + r] + bhh[l * G4 + r];
        } else if (j < 4096 + 10240) {
            int jj = j - 4096;
            int nb = jj / 320, rem = jj % 320, nl = rem / 10, e = rem % 10;
            int r = (nl >> 3) * 256 + nb * 8 + (nl & 7);
            g_w0p[jj] = Wih0[r * E + e];
        }
    }
}

// ---------------- prep 2: s = relu((e01[x]+p01) @ f01_w.T + f01_b) ----------------
__global__ void k_embed(const int* __restrict__ x, const float* __restrict__ e01,
                        const float* __restrict__ p01, const float* __restrict__ f01w,
                        const float* __restrict__ f01b) {
    int idx = blockIdx.x * 256 + threadIdx.x;
    if (idx >= S * B) return;
    int t = idx / B;
    int tok = x[idx];
    float v[E];
#pragma unroll
    for (int e = 0; e < E; e++) v[e] = e01[tok * E + e] + p01[t * E + e];
    float* so = g_S + (size_t)idx * E;
#pragma unroll
    for (int i = 0; i < E; i++) {
        float a = f01b[i];
#pragma unroll
        for (int e = 0; e < E; e++) a += v[e] * f01w[i * E + e];
        so[i] = fmaxf(a, 0.0f);
    }
}

// ---------------- prep 3: ssum + h0/c0 + counter reset (fused) ----------------
__global__ void k_ssum_init(const float* __restrict__ f02w, const float* __restrict__ f02b,
                            const float* __restrict__ f03w, const float* __restrict__ f03b) {
    __shared__ float red[256 * E];
    __shared__ float ss[E];
    int b = blockIdx.x, tid = threadIdx.x;
    float acc[E];
#pragma unroll
    for (int e = 0; e < E; e++) acc[e] = 0.0f;
    for (int t = tid; t < S; t += 256) {
        const float* sp = g_S + ((size_t)t * B + b) * E;
#pragma unroll
        for (int e = 0; e < E; e++) acc[e] += sp[e];
    }
#pragma unroll
    for (int e = 0; e < E; e++) red[tid * E + e] = acc[e];
    __syncthreads();
    for (int s = 128; s > 0; s >>= 1) {
        if (tid < s) {
#pragma unroll
            for (int e = 0; e < E; e++) red[tid * E + e] += red[(tid + s) * E + e];
        }
        __syncthreads();
    }
    if (tid < E) ss[tid] = red[tid];
    if (b == 0 && tid < L * NW) g_cnt[tid] = 0;
    __syncthreads();
    __nv_bfloat16* Hb = (__nv_bfloat16*)g_Hq;
#pragma unroll
    for (int i = 0; i < 4; i++) {
        int r = tid + i * 256;           // gate row 0..1023
        float ah = f02b[r], ac = f03b[r];
#pragma unroll
        for (int e = 0; e < E; e++) {
            ah += ss[e] * f02w[r * E + e];
            ac += ss[e] * f03w[r * E + e];
        }
        ah = fmaxf(ah, 0.0f);
        ac = fmaxf(ac, 0.0f);
        int l = r >> 8, j = r & 255;
        int u = unitj(j & ~1);
        // initial h = "step -1" output -> slot 2
        size_t base = (((size_t)(l * 3 + 2) * B) + b) * 512 + u * 4 + (j & 1);
        __nv_bfloat16 hh = __float2bfloat16(ah);
        Hb[base]     = hh;
        Hb[base + 2] = __float2bfloat16(ah - __bfloat162float(hh));
        g_C0[((size_t)l * B + b) * H + j] = ac;
    }
}

// ---------------- persistent recurrent kernel: per-warp decoupled pipeline ----------------
__global__ void __launch_bounds__(128, 1) lstm_rec(float* __restrict__ out) {
    const int bid = blockIdx.x;
    const int l   = bid >> 5;
    const int nb  = bid & 31;
    const int tid = threadIdx.x;
    const int warp = tid >> 5;
    const int lane = tid & 31;

    extern __shared__ unsigned char smem[];
    uint4* Wsm  = (uint4*)smem;                 // [32][4][32] uint4 = 64KB
    float* bsm  = (float*)(Wsm + 4096);         // 32
    float* w0sm = bsm + 32;                     // 320 (layer 0 only)

    const int Kkt = (l == 0) ? 16 : 32;
    {
        const uint4* src = g_Wp + (size_t)(l * 32 + nb) * 4096;
        for (int i = tid; i < Kkt * 128; i += 128) Wsm[i] = src[i];
        if (tid < 32) bsm[tid] = g_bias[(l * 32 + nb) * 32 + tid];
        if (l == 0) for (int i = tid; i < 320; i += 128) w0sm[i] = g_w0p[nb * 320 + i];
    }

    const int qd  = lane & 3;
    const int r0  = lane >> 2;
    const int c2  = qd * 2;
    const int b0  = warp * 32 + r0;             // frag0 base row; frag1 at +16
    const int jj0 = nb * 8 + c2;
    const int ust = unitj(jj0);                 // store unit within row

    float cst[2][4];
#pragma unroll
    for (int f = 0; f < 2; f++) {
        int rb = b0 + f * 16;
        cst[f][0] = g_C0[((size_t)l * B + rb) * H + jj0];
        cst[f][1] = g_C0[((size_t)l * B + rb) * H + jj0 + 1];
        cst[f][2] = g_C0[((size_t)l * B + rb + 8) * H + jj0];
        cst[f][3] = g_C0[((size_t)l * B + rb + 8) * H + jj0 + 1];
    }
    __syncthreads();

    // per-lane smem weight pointers
    const uint4* WqIn  = Wsm + lane;                       // input half (l>0): kt 0..15
    const uint4* WqOwn = Wsm + (l ? 16 * 128 : 0) + lane;  // Whh half

    int* cOwn = &g_cnt[l * NW + warp];
    int* cIn  = (l > 0) ? &g_cnt[(l - 1) * NW + warp] : nullptr;
    int* cDn  = (l < 3) ? &g_cnt[(l + 1) * NW + warp] : nullptr;

    const size_t laneOfs = (size_t)b0 * 64 + qd;
    int scur = 0, sprev = 2;

    float bias_r[4][2];
#pragma unroll
    for (int nt = 0; nt < 4; nt++) {
        bias_r[nt][0] = bsm[nt * 8 + c2];
        bias_r[nt][1] = bsm[nt * 8 + c2 + 1];
    }

    for (int t = 0; t < S; ++t) {
        float acc[2][4][4];
#pragma unroll
        for (int f = 0; f < 2; f++)
#pragma unroll
            for (int nt = 0; nt < 4; nt++)
#pragma unroll
                for (int rg = 0; rg < 4; rg++)
                    acc[f][nt][rg] = bias_r[nt][rg & 1];

        if (l == 0) {  // E=10 input contribution (independent of all counters)
#pragma unroll
            for (int f = 0; f < 2; f++) {
                float sv0[E], sv1[E];
                const float* sp = g_S + ((size_t)t * B + b0 + f * 16) * E;
#pragma unroll
                for (int e = 0; e < E; e++) { sv0[e] = sp[e]; sv1[e] = sp[8 * E + e]; }
#pragma unroll
                for (int nt = 0; nt < 4; nt++) {
                    const float* wA = w0sm + (nt * 8 + c2) * E;
                    const float* wB = wA + E;
#pragma unroll
                    for (int e = 0; e < E; e++) {
                        acc[f][nt][0] += sv0[e] * wA[e];
                        acc[f][nt][1] += sv0[e] * wB[e];
                        acc[f][nt][2] += sv1[e] * wA[e];
                        acc[f][nt][3] += sv1[e] * wB[e];
                    }
                }
            }
        }

        // wait: own layer step t-1 done by all 32 blocks
        if (t > 0)           while (ld_acq(cOwn) < 32 * t) { }
        // anti-overwrite: layer above consumed h[t-3]
        if (l < 3 && t >= 3) while (ld_acq(cDn) < 32 * (t - 2)) { }

        // Whh half (own h from step t-1, slot sprev)
        do_half(g_Hq + (size_t)(l * 3 + sprev) * B * 64 + laneOfs, WqOwn, acc);

        // input half (layer l-1 h from step t, slot scur)
        if (l > 0) {
            while (ld_acq(cIn) < 32 * (t + 1)) { }
            do_half(g_Hq + (size_t)((l - 1) * 3 + scur) * B * 64 + laneOfs, WqIn, acc);
        }

        // epilogue
        unsigned long long* Ow =
            (unsigned long long*)(g_Hq + (size_t)(l * 3 + scur) * B * 64);
#pragma unroll
        for (int f = 0; f < 2; f++) {
            float hv[4];
#pragma unroll
            for (int rg = 0; rg < 4; rg++) {
                float iv = fsig(acc[f][0][rg]);
                float fv = fsig(acc[f][1][rg]);
                float gv = ftanh(acc[f][2][rg]);
                float ov = fsig(acc[f][3][rg]);
                float cv = fv * cst[f][rg] + iv * gv;
                cst[f][rg] = cv;
                hv[rg] = ov * ftanh(cv);
            }
#pragma unroll
            for (int half = 0; half < 2; half++) {
                float h0v = hv[half * 2], h1v = hv[half * 2 + 1];
                int row = b0 + f * 16 + half * 8;
                __nv_bfloat16 hh0 = __float2bfloat16(h0v);
                __nv_bfloat16 hh1 = __float2bfloat16(h1v);
                unsigned lo32 = pk(hh0, hh1);
                unsigned hi32 = pk(__float2bfloat16(h0v - __bfloat162float(hh0)),
                                   __float2bfloat16(h1v - __bfloat162float(hh1)));
                unsigned long long val = (unsigned long long)lo32 |
                                         ((unsigned long long)hi32 << 32);
                Ow[(size_t)row * 128 + ust] = val;
                if (t == S - 1) {
                    float2 o2 = make_float2(h0v, h1v);
                    *(float2*)(out + (size_t)row * G4 + l * H + jj0) = o2;
                }
            }
        }

        __syncwarp();
        if (lane == 0) red_rel(cOwn, 1);

        sprev = scur;
        scur = (scur == 2) ? 0 : scur + 1;
    }
}

// ---------------- launch ----------------
extern "C" void kernel_launch(void* const* d_in, const int* in_sizes, int n_in,
                              void* d_out, int out_size) {
    const int*   x    = (const int*)d_in[0];
    const float* e01  = (const float*)d_in[1];
    const float* p01  = (const float*)d_in[2];
    const float* f01w = (const float*)d_in[3];
    const float* f01b = (const float*)d_in[4];
    const float* f02w = (const float*)d_in[5];
    const float* f02b = (const float*)d_in[6];
    const float* f03w = (const float*)d_in[7];
    const float* f03b = (const float*)d_in[8];
    const float* Wih0 = (const float*)d_in[9];
    const float* Wihr = (const float*)d_in[10];
    const float* Whh  = (const float*)d_in[11];
    const float* bih  = (const float*)d_in[12];
    const float* bhh  = (const float*)d_in[13];
    float* out = (float*)d_out;

    k_prep<<<(4 * 32 * 32 * 4 * 32 + 4096 + 10240 + 255) / 256, 256>>>(Wih0, Wihr, Whh, bih, bhh);
    k_embed<<<(S * B + 255) / 256, 256>>>(x, e01, p01, f01w, f01b);
    k_ssum_init<<<B, 256>>>(f02w, f02b, f03w, f03b);

    const int smem_bytes = 4096 * 16 + (32 + 320) * 4;  // 66944
    cudaFuncSetAttribute(lstm_rec, cudaFuncAttributeMaxDynamicSharedMemorySize,
                         smem_bytes);
    lstm_rec<<<NBLK, 128, smem_bytes>>>(out);
}

// round 7
// speedup vs baseline: 1.2097x; 1.2097x over previous
#include <cuda_runtime.h>
#include <cuda_bf16.h>
#include <math.h>

#define S 1024
#define B 128
#define E 10
#define H 256
#define L 4
#define G4 1024           // 4*H
#define NBPL 32           // blocks per layer
#define NBLK (NBPL * L)   // 128 persistent blocks
#define EXSTR 34          // exchange buffer row stride (floats), even for float2 align

// ---------------- device scratch (static; no allocations) ----------------
// weight fragments: [l][nb][kt][nt][lane] = uint4(whi.x, whi.y, wlo.x, wlo.y)
__device__ __align__(16) uint4  g_Wp[4 * 32 * 32 * 4 * 32];
__device__ float  g_bias[4 * 32 * 32];
__device__ float  g_w0p[32 * 32 * 10];
__device__ float  g_S[S * B * E];
__device__ float  g_C0[L * B * H];
// h state: [l][slot(3)][b][64 uint4]; unit u64 = (hi(j),hi(j+1),lo(j),lo(j+1))
__device__ __align__(16) uint4 g_Hq[L * 3 * B * 64];
__device__ int g_cnt2[L * 2];   // per (layer, m-half) counters; +128 per step

// ---------------- helpers ----------------
__device__ __host__ __forceinline__ int unitj(int j) {
    return (j >> 4) * 8 + (((j & 6) >> 1) << 1) + ((j >> 3) & 1);
}

__device__ __forceinline__ unsigned pk(__nv_bfloat16 a, __nv_bfloat16 b) {
    __nv_bfloat162 t; t.x = a; t.y = b;
    return *reinterpret_cast<unsigned*>(&t);
}

__device__ __forceinline__ void mma16816(float c[4], const unsigned a[4],
                                         unsigned b0, unsigned b1) {
    asm volatile(
        "mma.sync.aligned.m16n8k16.row.col.f32.bf16.bf16.f32 "
        "{%0,%1,%2,%3},{%4,%5,%6,%7},{%8,%9},{%0,%1,%2,%3};"
        : "+f"(c[0]), "+f"(c[1]), "+f"(c[2]), "+f"(c[3])
        : "r"(a[0]), "r"(a[1]), "r"(a[2]), "r"(a[3]), "r"(b0), "r"(b1));
}

__device__ __forceinline__ float fsig(float x) {
    return __fdividef(1.0f, 1.0f + __expf(-x));
}
__device__ __forceinline__ float ftanh(float x) {
    return 1.0f - __fdividef(2.0f, __expf(2.0f * x) + 1.0f);
}

__device__ __forceinline__ int ld_acq(const int* p) {
    int v;
    asm volatile("ld.acquire.gpu.global.b32 %0, [%1];" : "=r"(v) : "l"(p) : "memory");
    return v;
}
__device__ __forceinline__ void red_rel(int* p, int v) {
    asm volatile("red.release.gpu.global.add.s32 [%0], %1;" :: "l"(p), "r"(v) : "memory");
}

// ---------------- prep 1: pack weights + biases + layer0 Wih ----------------
__global__ void k_prep(const float* __restrict__ Wih0, const float* __restrict__ Wihr,
                       const float* __restrict__ Whh,  const float* __restrict__ bih,
                       const float* __restrict__ bhh) {
    int idx = blockIdx.x * 256 + threadIdx.x;
    if (idx < 4 * 32 * 32 * 4 * 32) {
        int lane = idx & 31;
        int nt   = (idx >> 5) & 3;
        int kt   = (idx >> 7) & 31;
        int nb   = (idx >> 12) & 31;
        int l    = idx >> 17;
        if (l == 0 && kt >= 16) return;
        int ncol = lane >> 2;
        int r    = nt * 256 + nb * 8 + ncol;
        int k0   = kt * 16 + (lane & 3) * 2;
        __nv_bfloat16 hi[4], lo[4];
#pragma unroll
        for (int q = 0; q < 4; q++) {
            int k = k0 + (q >> 1) * 8 + (q & 1);   // k0,k0+1,k0+8,k0+9
            float w;
            if (l == 0)       w = Whh[(size_t)r * H + k];
            else if (k < H)   w = Wihr[(size_t)((l - 1) * G4 + r) * H + k];
            else              w = Whh[(size_t)(l * G4 + r) * H + (k - H)];
            hi[q] = __float2bfloat16(w);
            lo[q] = __float2bfloat16(w - __bfloat162float(hi[q]));
        }
        g_Wp[idx] = make_uint4(pk(hi[0], hi[1]), pk(hi[2], hi[3]),
                               pk(lo[0], lo[1]), pk(lo[2], lo[3]));
    } else {
        int j = idx - 4 * 32 * 32 * 4 * 32;
        if (j < 4096) {
            int l = j >> 10, nb = (j >> 5) & 31, nl = j & 31;
            int r = (nl >> 3) * 256 + nb * 8 + (nl & 7);
            g_bias[j] = bih[l * G4 + r] + bhh[l * G4 + r];
        } else if (j < 4096 + 10240) {
            int jj = j - 4096;
            int nb = jj / 320, rem = jj % 320, nl = rem / 10, e = rem % 10;
            int r = (nl >> 3) * 256 + nb * 8 + (nl & 7);
            g_w0p[jj] = Wih0[r * E + e];
        }
    }
}

// ---------------- prep 2: s = relu((e01[x]+p01) @ f01_w.T + f01_b) ----------------
__global__ void k_embed(const int* __restrict__ x, const float* __restrict__ e01,
                        const float* __restrict__ p01, const float* __restrict__ f01w,
                        const float* __restrict__ f01b) {
    int idx = blockIdx.x * 256 + threadIdx.x;
    if (idx >= S * B) return;
    int t = idx / B;
    int tok = x[idx];
    float v[E];
#pragma unroll
    for (int e = 0; e < E; e++) v[e] = e01[tok * E + e] + p01[t * E + e];
    float* so = g_S + (size_t)idx * E;
#pragma unroll
    for (int i = 0; i < E; i++) {
        float a = f01b[i];
#pragma unroll
        for (int e = 0; e < E; e++) a += v[e] * f01w[i * E + e];
        so[i] = fmaxf(a, 0.0f);
    }
}

// ---------------- prep 3: ssum + h0/c0 + counter reset (fused) ----------------
__global__ void k_ssum_init(const float* __restrict__ f02w, const float* __restrict__ f02b,
                            const float* __restrict__ f03w, const float* __restrict__ f03b) {
    __shared__ float red[256 * E];
    __shared__ float ss[E];
    int b = blockIdx.x, tid = threadIdx.x;
    float acc[E];
#pragma unroll
    for (int e = 0; e < E; e++) acc[e] = 0.0f;
    for (int t = tid; t < S; t += 256) {
        const float* sp = g_S + ((size_t)t * B + b) * E;
#pragma unroll
        for (int e = 0; e < E; e++) acc[e] += sp[e];
    }
#pragma unroll
    for (int e = 0; e < E; e++) red[tid * E + e] = acc[e];
    __syncthreads();
    for (int s = 128; s > 0; s >>= 1) {
        if (tid < s) {
#pragma unroll
            for (int e = 0; e < E; e++) red[tid * E + e] += red[(tid + s) * E + e];
        }
        __syncthreads();
    }
    if (tid < E) ss[tid] = red[tid];
    if (b == 0 && tid < L * 2) g_cnt2[tid] = 0;
    __syncthreads();
    __nv_bfloat16* Hb = (__nv_bfloat16*)g_Hq;
#pragma unroll
    for (int i = 0; i < 4; i++) {
        int r = tid + i * 256;           // gate row 0..1023
        float ah = f02b[r], ac = f03b[r];
#pragma unroll
        for (int e = 0; e < E; e++) {
            ah += ss[e] * f02w[r * E + e];
            ac += ss[e] * f03w[r * E + e];
        }
        ah = fmaxf(ah, 0.0f);
        ac = fmaxf(ac, 0.0f);
        int l = r >> 8, j = r & 255;
        int u = unitj(j & ~1);
        // initial h = "step -1" output -> slot 2
        size_t base = (((size_t)(l * 3 + 2) * B) + b) * 512 + u * 4 + (j & 1);
        __nv_bfloat16 hh = __float2bfloat16(ah);
        Hb[base]     = hh;
        Hb[base + 2] = __float2bfloat16(ah - __bfloat162float(hh));
        g_C0[((size_t)l * B + b) * H + j] = ac;
    }
}

// ---------------- main recurrence body (templated on K-slice count) ----------------
// 8 warps = 2 m-groups (m64) x 4 k-groups (NKT kts each). Weights live in registers.
// Cross-k reduction via smem exchange; epilogue warp w owns rows [w*16, w*16+16).
template<int NKT, bool HASIN>
__device__ __forceinline__ void run_loop(int l, int nb, int warp, int lane,
                                         float* ex, const float* w0sm,
                                         float* __restrict__ out) {
    const int kg = warp & 3, mg = warp >> 2;
    const int qd = lane & 3, r0 = lane >> 2, c2 = qd * 2;

    const bool isIn  = HASIN && (kg < 2);
    const int ktloc0 = HASIN ? ((kg < 2) ? kg * 8 : (kg - 2) * 8) : kg * 4;
    const int ktglob0 = HASIN ? kg * 8 : kg * 4;

    // one-time: weights into registers
    uint4 wreg[NKT][4];
    {
        const uint4* wp = g_Wp + (size_t)(l * 32 + nb) * 4096 + lane;
#pragma unroll
        for (int j = 0; j < NKT; j++)
#pragma unroll
            for (int nt = 0; nt < 4; nt++)
                wreg[j][nt] = wp[(ktglob0 + j) * 128 + nt * 32];
    }

    // epilogue constants
    const int eb0 = warp * 16 + r0;
    const int jj0 = nb * 8 + c2;
    const int ust = unitj(jj0);
    float bias_r[4][2];
#pragma unroll
    for (int nt = 0; nt < 4; nt++) {
        bias_r[nt][0] = g_bias[(l * 32 + nb) * 32 + nt * 8 + c2];
        bias_r[nt][1] = g_bias[(l * 32 + nb) * 32 + nt * 8 + c2 + 1];
    }
    float cst[4];
    cst[0] = g_C0[((size_t)l * B + eb0) * H + jj0];
    cst[1] = g_C0[((size_t)l * B + eb0) * H + jj0 + 1];
    cst[2] = g_C0[((size_t)l * B + eb0 + 8) * H + jj0];
    cst[3] = g_C0[((size_t)l * B + eb0 + 8) * H + jj0 + 1];

    int rowOfs[4];
#pragma unroll
    for (int f = 0; f < 4; f++) rowOfs[f] = (mg * 64 + f * 16 + r0) * 64 + qd;

    int* cOwn = &g_cnt2[l * 2 + mg];
    int* cIn  = HASIN ? &g_cnt2[(l - 1) * 2 + mg] : nullptr;
    int* cDn  = (l < 3) ? &g_cnt2[(l + 1) * 2 + mg] : nullptr;

    int scur = 0, sprev = 2;

    for (int t = 0; t < S; ++t) {
        // producer-role poll
        if (isIn) {
            while (ld_acq(cIn) < 128 * (t + 1)) { }
        } else if (t > 0) {
            while (ld_acq(cOwn) < 128 * t) { }
        }

        const uint4* Hs = g_Hq +
            (size_t)(isIn ? ((l - 1) * 3 + scur) : (l * 3 + sprev)) * B * 64;

        float acc[4][4][4];
#pragma unroll
        for (int f = 0; f < 4; f++)
#pragma unroll
            for (int nt = 0; nt < 4; nt++)
#pragma unroll
                for (int rg = 0; rg < 4; rg++) acc[f][nt][rg] = 0.0f;

#pragma unroll
        for (int j = 0; j < NKT; j++) {
            const int ko = (ktloc0 + j) * 4;
#pragma unroll
            for (int f = 0; f < 4; f++) {
                const uint4* p = Hs + rowOfs[f] + ko;
                uint4 u1 = __ldcg(p);
                uint4 u2 = __ldcg(p + 8 * 64);
                unsigned a[4]  = {u1.x, u2.x, u1.z, u2.z};
                unsigned al[4] = {u1.y, u2.y, u1.w, u2.w};
                // pass 1: Ahi * Whi
                mma16816(acc[f][0], a, wreg[j][0].x, wreg[j][0].y);
                mma16816(acc[f][1], a, wreg[j][1].x, wreg[j][1].y);
                mma16816(acc[f][2], a, wreg[j][2].x, wreg[j][2].y);
                mma16816(acc[f][3], a, wreg[j][3].x, wreg[j][3].y);
                // pass 2: Alo * Whi
                mma16816(acc[f][0], al, wreg[j][0].x, wreg[j][0].y);
                mma16816(acc[f][1], al, wreg[j][1].x, wreg[j][1].y);
                mma16816(acc[f][2], al, wreg[j][2].x, wreg[j][2].y);
                mma16816(acc[f][3], al, wreg[j][3].x, wreg[j][3].y);
                // pass 3: Ahi * Wlo
                mma16816(acc[f][0], a, wreg[j][0].z, wreg[j][0].w);
                mma16816(acc[f][1], a, wreg[j][1].z, wreg[j][1].w);
                mma16816(acc[f][2], a, wreg[j][2].z, wreg[j][2].w);
                mma16816(acc[f][3], a, wreg[j][3].z, wreg[j][3].w);
            }
        }

        // store partials to exchange buffer
#pragma unroll
        for (int f = 0; f < 4; f++) {
            int r1 = mg * 64 + f * 16 + r0;
#pragma unroll
            for (int nt = 0; nt < 4; nt++) {
                int c = nt * 8 + c2;
                *(float2*)&ex[(kg * 128 + r1) * EXSTR + c] =
                    make_float2(acc[f][nt][0], acc[f][nt][1]);
                *(float2*)&ex[(kg * 128 + r1 + 8) * EXSTR + c] =
                    make_float2(acc[f][nt][2], acc[f][nt][3]);
            }
        }
        __syncthreads();

        // epilogue-role: reduce over 4 k-groups for rows [eb0, eb0+8]
        float a4[4][4];
#pragma unroll
        for (int nt = 0; nt < 4; nt++) {
            int c = nt * 8 + c2;
            float2 s0 = make_float2(0.f, 0.f), s1 = make_float2(0.f, 0.f);
#pragma unroll
            for (int k2 = 0; k2 < 4; k2++) {
                float2 v0 = *(const float2*)&ex[(k2 * 128 + eb0) * EXSTR + c];
                float2 v1 = *(const float2*)&ex[(k2 * 128 + eb0 + 8) * EXSTR + c];
                s0.x += v0.x; s0.y += v0.y; s1.x += v1.x; s1.y += v1.y;
            }
            a4[nt][0] = bias_r[nt][0] + s0.x;
            a4[nt][1] = bias_r[nt][1] + s0.y;
            a4[nt][2] = bias_r[nt][0] + s1.x;
            a4[nt][3] = bias_r[nt][1] + s1.y;
        }
        __syncthreads();   // exchange buffer free for next step

        if (!HASIN) {  // layer 0: E=10 input contribution
            float sv0[E], sv1[E];
            const float* sp = g_S + ((size_t)t * B + eb0) * E;
#pragma unroll
            for (int e = 0; e < E; e++) { sv0[e] = sp[e]; sv1[e] = sp[8 * E + e]; }
#pragma unroll
            for (int nt = 0; nt < 4; nt++) {
                const float* wA = w0sm + (nt * 8 + c2) * E;
                const float* wB = wA + E;
#pragma unroll
                for (int e = 0; e < E; e++) {
                    a4[nt][0] += sv0[e] * wA[e];
                    a4[nt][1] += sv0[e] * wB[e];
                    a4[nt][2] += sv1[e] * wA[e];
                    a4[nt][3] += sv1[e] * wB[e];
                }
            }
        }

        // anti-overwrite: layer above consumed h[t-3]
        if (l < 3 && t >= 3) while (ld_acq(cDn) < 128 * (t - 2)) { }

        float hv[4];
#pragma unroll
        for (int rg = 0; rg < 4; rg++) {
            float iv = fsig(a4[0][rg]);
            float fv = fsig(a4[1][rg]);
            float gv = ftanh(a4[2][rg]);
            float ov = fsig(a4[3][rg]);
            float cv = fv * cst[rg] + iv * gv;
            cst[rg] = cv;
            hv[rg] = ov * ftanh(cv);
        }

        unsigned long long* Ow =
            (unsigned long long*)(g_Hq + (size_t)(l * 3 + scur) * B * 64);
#pragma unroll
        for (int half = 0; half < 2; half++) {
            float h0v = hv[half * 2], h1v = hv[half * 2 + 1];
            int row = eb0 + half * 8;
            __nv_bfloat16 hh0 = __float2bfloat16(h0v);
            __nv_bfloat16 hh1 = __float2bfloat16(h1v);
            unsigned lo32 = pk(hh0, hh1);
            unsigned hi32 = pk(__float2bfloat16(h0v - __bfloat162float(hh0)),
                               __float2bfloat16(h1v - __bfloat162float(hh1)));
            unsigned long long val = (unsigned long long)lo32 |
                                     ((unsigned long long)hi32 << 32);
            Ow[(size_t)row * 128 + ust] = val;
            if (t == S - 1) {
                float2 o2 = make_float2(h0v, h1v);
                *(float2*)(out + (size_t)row * G4 + l * H + jj0) = o2;
            }
        }

        __syncwarp();
        if (lane == 0) red_rel(cOwn, 1);

        sprev = scur;
        scur = (scur == 2) ? 0 : scur + 1;
    }
}

// ---------------- persistent recurrent kernel ----------------
__global__ void __launch_bounds__(256, 1) lstm_rec(float* __restrict__ out) {
    const int bid = blockIdx.x;
    const int l   = bid >> 5;
    const int nb  = bid & 31;
    const int tid = threadIdx.x;

    extern __shared__ unsigned char smem[];
    float* ex   = (float*)smem;                 // 4*128*EXSTR floats
    float* w0sm = ex + 4 * 128 * EXSTR;         // 320 (layer 0 only)

    if (l == 0) for (int i = tid; i < 320; i += 256) w0sm[i] = g_w0p[nb * 320 + i];
    __syncthreads();

    if (l == 0) run_loop<4, false>(l, nb, tid >> 5, tid & 31, ex, w0sm, out);
    else        run_loop<8, true >(l, nb, tid >> 5, tid & 31, ex, w0sm, out);
}

// ---------------- launch ----------------
extern "C" void kernel_launch(void* const* d_in, const int* in_sizes, int n_in,
                              void* d_out, int out_size) {
    const int*   x    = (const int*)d_in[0];
    const float* e01  = (const float*)d_in[1];
    const float* p01  = (const float*)d_in[2];
    const float* f01w = (const float*)d_in[3];
    const float* f01b = (const float*)d_in[4];
    const float* f02w = (const float*)d_in[5];
    const float* f02b = (const float*)d_in[6];
    const float* f03w = (const float*)d_in[7];
    const float* f03b = (const float*)d_in[8];
    const float* Wih0 = (const float*)d_in[9];
    const float* Wihr = (const float*)d_in[10];
    const float* Whh  = (const float*)d_in[11];
    const float* bih  = (const float*)d_in[12];
    const float* bhh  = (const float*)d_in[13];
    float* out = (float*)d_out;

    k_prep<<<(4 * 32 * 32 * 4 * 32 + 4096 + 10240 + 255) / 256, 256>>>(Wih0, Wihr, Whh, bih, bhh);
    k_embed<<<(S * B + 255) / 256, 256>>>(x, e01, p01, f01w, f01b);
    k_ssum_init<<<B, 256>>>(f02w, f02b, f03w, f03b);

    const int smem_bytes = (4 * 128 * EXSTR + 320) * 4;  // ~70KB
    cudaFuncSetAttribute(lstm_rec, cudaFuncAttributeMaxDynamicSharedMemorySize,
                         smem_bytes);
    lstm_rec<<<NBLK, 256, smem_bytes>>>(out);
}

// round 8
// speedup vs baseline: 1.5608x; 1.2902x over previous
#include <cuda_runtime.h>
#include <cuda_fp16.h>
#include <math.h>

#define S 1024
#define B 128
#define E 10
#define H 256
#define L 4
#define G4 1024           // 4*H
#define NBPL 32           // blocks per layer
#define NBLK (NBPL * L)   // 128 persistent blocks

// ---------------- device scratch (static; no allocations) ----------------
// fp16 weight fragments: [l][nb][kt][nt][lane] = uint2(w.k01, w.k89)
__device__ __align__(8) uint2  g_Wp[4 * 32 * 32 * 4 * 32];
__device__ float  g_bias[4 * 32 * 32];
__device__ float  g_w0p[32 * 32 * 10];
__device__ float  g_S[S * B * E];
__device__ float  g_C0[L * B * H];
// h state: [l][slot(3)][b][64 uint4]; u64 unit = (hi(j),hi(j+1),lo(j),lo(j+1)) fp16
__device__ __align__(16) uint4 g_Hq[L * 3 * B * 64];
__device__ int g_cnt[L * 8];   // per (layer, warp) completed-step counters (x32 blocks)

// ---------------- helpers ----------------
// perm-unit index for even col j: u64-unit within row
__device__ __host__ __forceinline__ int unitj(int j) {
    return (j >> 4) * 8 + (j & 6) + ((j >> 3) & 1);
}

__device__ __forceinline__ unsigned pk(__half a, __half b) {
    __half2 t; t.x = a; t.y = b;
    return *reinterpret_cast<unsigned*>(&t);
}

__device__ __forceinline__ void mma16816(float c[4], const unsigned a[4],
                                         unsigned b0, unsigned b1) {
    asm volatile(
        "mma.sync.aligned.m16n8k16.row.col.f32.f16.f16.f32 "
        "{%0,%1,%2,%3},{%4,%5,%6,%7},{%8,%9},{%0,%1,%2,%3};"
        : "+f"(c[0]), "+f"(c[1]), "+f"(c[2]), "+f"(c[3])
        : "r"(a[0]), "r"(a[1]), "r"(a[2]), "r"(a[3]), "r"(b0), "r"(b1));
}

__device__ __forceinline__ float fsig(float x) {
    return __fdividef(1.0f, 1.0f + __expf(-x));
}
__device__ __forceinline__ float ftanh(float x) {
    return 1.0f - __fdividef(2.0f, __expf(2.0f * x) + 1.0f);
}

__device__ __forceinline__ int ld_acq(const int* p) {
    int v;
    asm volatile("ld.acquire.gpu.global.b32 %0, [%1];" : "=r"(v) : "l"(p) : "memory");
    return v;
}
__device__ __forceinline__ void red_rel(int* p, int v) {
    asm volatile("red.release.gpu.global.add.s32 [%0], %1;" :: "l"(p), "r"(v) : "memory");
}

// one 16-kt half of the K sweep (2-pass fp16); Hq = per-lane activation ptr (kt=0),
// Wq = per-lane smem ptr (kt=0)
__device__ __forceinline__ void do_half(const uint4* __restrict__ Hq,
                                        const uint2* __restrict__ Wq,
                                        float acc[4][4]) {
#pragma unroll
    for (int kt = 0; kt < 16; ++kt) {
        uint4 u1 = __ldcg(Hq + kt * 4);
        uint4 u2 = __ldcg(Hq + kt * 4 + 8 * 64);
        unsigned a[4]  = {u1.x, u2.x, u1.z, u2.z};
        unsigned al[4] = {u1.y, u2.y, u1.w, u2.w};
        uint2 w0 = Wq[kt * 128 + 0];
        uint2 w1 = Wq[kt * 128 + 32];
        uint2 w2 = Wq[kt * 128 + 64];
        uint2 w3 = Wq[kt * 128 + 96];
        // pass 1: Ahi * W
        mma16816(acc[0], a,  w0.x, w0.y);
        mma16816(acc[1], a,  w1.x, w1.y);
        mma16816(acc[2], a,  w2.x, w2.y);
        mma16816(acc[3], a,  w3.x, w3.y);
        // pass 2: Alo * W
        mma16816(acc[0], al, w0.x, w0.y);
        mma16816(acc[1], al, w1.x, w1.y);
        mma16816(acc[2], al, w2.x, w2.y);
        mma16816(acc[3], al, w3.x, w3.y);
    }
}

// ---------------- prep 1: pack weights + biases + layer0 Wih ----------------
__global__ void k_prep(const float* __restrict__ Wih0, const float* __restrict__ Wihr,
                       const float* __restrict__ Whh,  const float* __restrict__ bih,
                       const float* __restrict__ bhh) {
    int idx = blockIdx.x * 256 + threadIdx.x;
    if (idx < 4 * 32 * 32 * 4 * 32) {
        int lane = idx & 31;
        int nt   = (idx >> 5) & 3;
        int kt   = (idx >> 7) & 31;
        int nb   = (idx >> 12) & 31;
        int l    = idx >> 17;
        if (l == 0 && kt >= 16) return;
        int ncol = lane >> 2;
        int r    = nt * 256 + nb * 8 + ncol;
        int k0   = kt * 16 + (lane & 3) * 2;
        __half w4[4];
#pragma unroll
        for (int q = 0; q < 4; q++) {
            int k = k0 + (q >> 1) * 8 + (q & 1);   // k0,k0+1,k0+8,k0+9
            float w;
            if (l == 0)       w = Whh[(size_t)r * H + k];
            else if (k < H)   w = Wihr[(size_t)((l - 1) * G4 + r) * H + k];
            else              w = Whh[(size_t)(l * G4 + r) * H + (k - H)];
            w4[q] = __float2half(w);
        }
        g_Wp[idx] = make_uint2(pk(w4[0], w4[1]), pk(w4[2], w4[3]));
    } else {
        int j = idx - 4 * 32 * 32 * 4 * 32;
        if (j < 4096) {
            int l = j >> 10, nb = (j >> 5) & 31, nl = j & 31;
            int r = (nl >> 3) * 256 + nb * 8 + (nl & 7);
            g_bias[j] = bih[l * G4 + r] + bhh[l * G4 + r];
        } else if (j < 4096 + 10240) {
            int jj = j - 4096;
            int nb = jj / 320, rem = jj % 320, nl = rem / 10, e = rem % 10;
            int r = (nl >> 3) * 256 + nb * 8 + (nl & 7);
            g_w0p[jj] = Wih0[r * E + e];
        }
    }
}

// ---------------- prep 2: s = relu((e01[x]+p01) @ f01_w.T + f01_b) ----------------
__global__ void k_embed(const int* __restrict__ x, const float* __restrict__ e01,
                        const float* __restrict__ p01, const float* __restrict__ f01w,
                        const float* __restrict__ f01b) {
    int idx = blockIdx.x * 256 + threadIdx.x;
    if (idx >= S * B) return;
    int t = idx / B;
    int tok = x[idx];
    float v[E];
#pragma unroll
    for (int e = 0; e < E; e++) v[e] = e01[tok * E + e] + p01[t * E + e];
    float* so = g_S + (size_t)idx * E;
#pragma unroll
    for (int i = 0; i < E; i++) {
        float a = f01b[i];
#pragma unroll
        for (int e = 0; e < E; e++) a += v[e] * f01w[i * E + e];
        so[i] = fmaxf(a, 0.0f);
    }
}

// ---------------- prep 3: ssum + h0/c0 + counter reset (fused) ----------------
__global__ void k_ssum_init(const float* __restrict__ f02w, const float* __restrict__ f02b,
                            const float* __restrict__ f03w, const float* __restrict__ f03b) {
    __shared__ float red[256 * E];
    __shared__ float ss[E];
    int b = blockIdx.x, tid = threadIdx.x;
    float acc[E];
#pragma unroll
    for (int e = 0; e < E; e++) acc[e] = 0.0f;
    for (int t = tid; t < S; t += 256) {
        const float* sp = g_S + ((size_t)t * B + b) * E;
#pragma unroll
        for (int e = 0; e < E; e++) acc[e] += sp[e];
    }
#pragma unroll
    for (int e = 0; e < E; e++) red[tid * E + e] = acc[e];
    __syncthreads();
    for (int s = 128; s > 0; s >>= 1) {
        if (tid < s) {
#pragma unroll
            for (int e = 0; e < E; e++) red[tid * E + e] += red[(tid + s) * E + e];
        }
        __syncthreads();
    }
    if (tid < E) ss[tid] = red[tid];
    if (b == 0 && tid < L * 8) g_cnt[tid] = 0;
    __syncthreads();
    __half* Hb = (__half*)g_Hq;
#pragma unroll
    for (int i = 0; i < 4; i++) {
        int r = tid + i * 256;           // gate row 0..1023
        float ah = f02b[r], ac = f03b[r];
#pragma unroll
        for (int e = 0; e < E; e++) {
            ah += ss[e] * f02w[r * E + e];
            ac += ss[e] * f03w[r * E + e];
        }
        ah = fmaxf(ah, 0.0f);
        ac = fmaxf(ac, 0.0f);
        int l = r >> 8, j = r & 255;
        int u = unitj(j & ~1);
        // initial h = "step -1" output -> slot 2
        size_t base = (((size_t)(l * 3 + 2) * B) + b) * 512 + u * 4 + (j & 1);
        __half hh = __float2half(ah);
        Hb[base]     = hh;
        Hb[base + 2] = __float2half(ah - __half2float(hh));
        g_C0[((size_t)l * B + b) * H + j] = ac;
    }
}

// ---------------- persistent recurrent kernel: per-warp decoupled pipeline ----------------
__global__ void __launch_bounds__(256, 1) lstm_rec(float* __restrict__ out) {
    const int bid = blockIdx.x;
    const int l   = bid >> 5;
    const int nb  = bid & 31;
    const int tid = threadIdx.x;
    const int warp = tid >> 5;
    const int lane = tid & 31;

    extern __shared__ unsigned char smem[];
    uint2* Wsm  = (uint2*)smem;                 // [32][4][32] uint2 = 32KB
    float* bsm  = (float*)(Wsm + 4096);         // 32
    float* w0sm = bsm + 32;                     // 320 (layer 0 only)

    const int Kkt = (l == 0) ? 16 : 32;
    {
        const uint2* src = g_Wp + (size_t)(l * 32 + nb) * 4096;
        for (int i = tid; i < Kkt * 128; i += 256) Wsm[i] = src[i];
        if (tid < 32) bsm[tid] = g_bias[(l * 32 + nb) * 32 + tid];
        if (l == 0) for (int i = tid; i < 320; i += 256) w0sm[i] = g_w0p[nb * 320 + i];
    }

    const int qd  = lane & 3;
    const int r0  = lane >> 2;
    const int c2  = qd * 2;
    const int b0  = warp * 16 + r0;
    const int jj0 = nb * 8 + c2;
    const int ust = unitj(jj0);                 // store unit within row

    float cst[4];
    cst[0] = g_C0[((size_t)l * B + b0) * H + jj0];
    cst[1] = g_C0[((size_t)l * B + b0) * H + jj0 + 1];
    cst[2] = g_C0[((size_t)l * B + b0 + 8) * H + jj0];
    cst[3] = g_C0[((size_t)l * B + b0 + 8) * H + jj0 + 1];
    __syncthreads();

    // per-lane smem weight pointers
    const uint2* WqIn  = Wsm + lane;                       // input half (l>0): kt 0..15
    const uint2* WqOwn = Wsm + (l ? 16 * 128 : 0) + lane;  // Whh half

    int* cOwn = &g_cnt[l * 8 + warp];
    int* cIn  = (l > 0) ? &g_cnt[(l - 1) * 8 + warp] : nullptr;
    int* cDn  = (l < 3) ? &g_cnt[(l + 1) * 8 + warp] : nullptr;

    // slot bases (uint4 index): slot s of layer l at (l*3+s)*B*64
    const size_t laneOfs = (size_t)b0 * 64 + qd;
    int scur = 0, sprev = 2;

    float bias_r[4][2];
#pragma unroll
    for (int nt = 0; nt < 4; nt++) {
        bias_r[nt][0] = bsm[nt * 8 + c2];
        bias_r[nt][1] = bsm[nt * 8 + c2 + 1];
    }

    for (int t = 0; t < S; ++t) {
        float acc[4][4];
#pragma unroll
        for (int nt = 0; nt < 4; nt++) {
#pragma unroll
            for (int rg = 0; rg < 4; rg++)
                acc[nt][rg] = bias_r[nt][rg & 1];
        }

        if (l == 0) {  // E=10 input contribution (independent of all counters)
            float sv0[E], sv1[E];
            const float* sp = g_S + ((size_t)t * B + b0) * E;
#pragma unroll
            for (int e = 0; e < E; e++) { sv0[e] = sp[e]; sv1[e] = sp[8 * E + e]; }
#pragma unroll
            for (int nt = 0; nt < 4; nt++) {
                const float* wA = w0sm + (nt * 8 + c2) * E;
                const float* wB = wA + E;
#pragma unroll
                for (int e = 0; e < E; e++) {
                    acc[nt][0] += sv0[e] * wA[e];
                    acc[nt][1] += sv0[e] * wB[e];
                    acc[nt][2] += sv1[e] * wA[e];
                    acc[nt][3] += sv1[e] * wB[e];
                }
            }
        }

        // wait: own layer step t-1 done by all 32 blocks (warp lane-uniform poll)
        if (t > 0)           while (ld_acq(cOwn) < 32 * t) { }
        // anti-overwrite: layer above consumed h[t-3]
        if (l < 3 && t >= 3) while (ld_acq(cDn) < 32 * (t - 2)) { }

        // Whh half (own h from step t-1, slot sprev)
        do_half(g_Hq + (size_t)(l * 3 + sprev) * B * 64 + laneOfs, WqOwn, acc);

        // input half (layer l-1 h from step t, slot scur)
        if (l > 0) {
            while (ld_acq(cIn) < 32 * (t + 1)) { }
            do_half(g_Hq + (size_t)((l - 1) * 3 + scur) * B * 64 + laneOfs, WqIn, acc);
        }

        // epilogue
        float hv[4];
#pragma unroll
        for (int rg = 0; rg < 4; rg++) {
            float iv = fsig(acc[0][rg]);
            float fv = fsig(acc[1][rg]);
            float gv = ftanh(acc[2][rg]);
            float ov = fsig(acc[3][rg]);
            float cv = fv * cst[rg] + iv * gv;
            cst[rg] = cv;
            hv[rg] = ov * ftanh(cv);
        }

        unsigned long long* Ow =
            (unsigned long long*)(g_Hq + (size_t)(l * 3 + scur) * B * 64);
#pragma unroll
        for (int half = 0; half < 2; half++) {
            float h0v = hv[half * 2], h1v = hv[half * 2 + 1];
            int row = b0 + half * 8;
            __half hh0 = __float2half(h0v);
            __half hh1 = __float2half(h1v);
            unsigned lo32 = pk(hh0, hh1);
            unsigned hi32 = pk(__float2half(h0v - __half2float(hh0)),
                               __float2half(h1v - __half2float(hh1)));
            unsigned long long val = (unsigned long long)lo32 |
                                     ((unsigned long long)hi32 << 32);
            Ow[(size_t)row * 128 + ust] = val;
            if (t == S - 1) {
                float2 o2 = make_float2(h0v, h1v);
                *(float2*)(out + (size_t)row * G4 + l * H + jj0) = o2;
            }
        }

        __syncwarp();
        if (lane == 0) red_rel(cOwn, 1);

        sprev = scur;
        scur = (scur == 2) ? 0 : scur + 1;
    }
}

// ---------------- launch ----------------
extern "C" void kernel_launch(void* const* d_in, const int* in_sizes, int n_in,
                              void* d_out, int out_size) {
    const int*   x    = (const int*)d_in[0];
    const float* e01  = (const float*)d_in[1];
    const float* p01  = (const float*)d_in[2];
    const float* f01w = (const float*)d_in[3];
    const float* f01b = (const float*)d_in[4];
    const float* f02w = (const float*)d_in[5];
    const float* f02b = (const float*)d_in[6];
    const float* f03w = (const float*)d_in[7];
    const float* f03b = (const float*)d_in[8];
    const float* Wih0 = (const float*)d_in[9];
    const float* Wihr = (const float*)d_in[10];
    const float* Whh  = (const float*)d_in[11];
    const float* bih  = (const float*)d_in[12];
    const float* bhh  = (const float*)d_in[13];
    float* out = (float*)d_out;

    k_prep<<<(4 * 32 * 32 * 4 * 32 + 4096 + 10240 + 255) / 256, 256>>>(Wih0, Wihr, Whh, bih, bhh);
    k_embed<<<(S * B + 255) / 256, 256>>>(x, e01, p01, f01w, f01b);
    k_ssum_init<<<B, 256>>>(f02w, f02b, f03w, f03b);

    const int smem_bytes = 4096 * 8 + (32 + 320) * 4;  // ~34KB
    cudaFuncSetAttribute(lstm_rec, cudaFuncAttributeMaxDynamicSharedMemorySize,
                         smem_bytes);
    lstm_rec<<<NBLK, 256, smem_bytes>>>(out);
}

// round 9
// speedup vs baseline: 1.6512x; 1.0579x over previous
#include <cuda_runtime.h>
#include <cuda_fp16.h>
#include <math.h>

#define S 1024
#define B 128
#define E 10
#define H 256
#define L 4
#define G4 1024           // 4*H
#define NBPL 32           // blocks per layer
#define NBLK (NBPL * L)   // 128 persistent blocks

// ---------------- device scratch (static; no allocations) ----------------
// fp16 weight fragments: [l][nb][kt][nt][lane] = uint2(w.k01, w.k89)
__device__ __align__(8) uint2  g_Wp[4 * 32 * 32 * 4 * 32];
__device__ float  g_bias[4 * 32 * 32];
__device__ float  g_w0p[32 * 32 * 10];
__device__ float  g_S[S * B * E];
__device__ float  g_C0[L * B * H];
// h state: [l][slot(3)][b][64 uint4]; u64 unit = (hi(j),hi(j+1),lo(j),lo(j+1)) fp16
__device__ __align__(16) uint4 g_Hq[L * 3 * B * 64];
__device__ int g_cnt[L * 8];   // per (layer, warp) completed-step counters (x32 blocks)

// ---------------- helpers ----------------
// perm-unit index for even col j: u64-unit within row
__device__ __host__ __forceinline__ int unitj(int j) {
    return (j >> 4) * 8 + (j & 6) + ((j >> 3) & 1);
}

__device__ __forceinline__ unsigned pk(__half a, __half b) {
    __half2 t; t.x = a; t.y = b;
    return *reinterpret_cast<unsigned*>(&t);
}

// NOTE: non-volatile asm, no memory clobber -> compiler may interleave with loads
__device__ __forceinline__ void mma16816(float c[4], const unsigned a[4],
                                         unsigned b0, unsigned b1) {
    asm("mma.sync.aligned.m16n8k16.row.col.f32.f16.f16.f32 "
        "{%0,%1,%2,%3},{%4,%5,%6,%7},{%8,%9},{%0,%1,%2,%3};"
        : "+f"(c[0]), "+f"(c[1]), "+f"(c[2]), "+f"(c[3])
        : "r"(a[0]), "r"(a[1]), "r"(a[2]), "r"(a[3]), "r"(b0), "r"(b1));
}

__device__ __forceinline__ float fsig(float x) {
    return __fdividef(1.0f, 1.0f + __expf(-x));
}
__device__ __forceinline__ float ftanh(float x) {
    return 1.0f - __fdividef(2.0f, __expf(2.0f * x) + 1.0f);
}

__device__ __forceinline__ int ld_acq(const int* p) {
    int v;
    asm volatile("ld.acquire.gpu.global.b32 %0, [%1];" : "=r"(v) : "l"(p) : "memory");
    return v;
}
__device__ __forceinline__ void red_rel(int* p, int v) {
    asm volatile("red.release.gpu.global.add.s32 [%0], %1;" :: "l"(p), "r"(v) : "memory");
}

// one 16-kt half of the K sweep (2-pass fp16), 4-deep activation prefetch.
// Hq = per-lane activation ptr (kt=0), Wq = per-lane smem ptr (kt=0)
__device__ __forceinline__ void do_half(const uint4* __restrict__ Hq,
                                        const uint2* __restrict__ Wq,
                                        float acc[4][4]) {
    uint4 pa[4], pb[4];
#pragma unroll
    for (int i = 0; i < 4; i++) {
        pa[i] = __ldcg(Hq + i * 4);
        pb[i] = __ldcg(Hq + i * 4 + 8 * 64);
    }
#pragma unroll
    for (int kt = 0; kt < 16; ++kt) {
        uint4 u1 = pa[kt & 3];
        uint4 u2 = pb[kt & 3];
        if (kt + 4 < 16) {
            pa[kt & 3] = __ldcg(Hq + (kt + 4) * 4);
            pb[kt & 3] = __ldcg(Hq + (kt + 4) * 4 + 8 * 64);
        }
        unsigned a[4]  = {u1.x, u2.x, u1.z, u2.z};
        unsigned al[4] = {u1.y, u2.y, u1.w, u2.w};
        uint2 w0 = Wq[kt * 128 + 0];
        uint2 w1 = Wq[kt * 128 + 32];
        uint2 w2 = Wq[kt * 128 + 64];
        uint2 w3 = Wq[kt * 128 + 96];
        // pass 1: Ahi * W
        mma16816(acc[0], a,  w0.x, w0.y);
        mma16816(acc[1], a,  w1.x, w1.y);
        mma16816(acc[2], a,  w2.x, w2.y);
        mma16816(acc[3], a,  w3.x, w3.y);
        // pass 2: Alo * W
        mma16816(acc[0], al, w0.x, w0.y);
        mma16816(acc[1], al, w1.x, w1.y);
        mma16816(acc[2], al, w2.x, w2.y);
        mma16816(acc[3], al, w3.x, w3.y);
    }
}

// ---------------- prep 1: pack weights + biases + layer0 Wih ----------------
__global__ void k_prep(const float* __restrict__ Wih0, const float* __restrict__ Wihr,
                       const float* __restrict__ Whh,  const float* __restrict__ bih,
                       const float* __restrict__ bhh) {
    int idx = blockIdx.x * 256 + threadIdx.x;
    if (idx < 4 * 32 * 32 * 4 * 32) {
        int lane = idx & 31;
        int nt   = (idx >> 5) & 3;
        int kt   = (idx >> 7) & 31;
        int nb   = (idx >> 12) & 31;
        int l    = idx >> 17;
        if (l == 0 && kt >= 16) return;
        int ncol = lane >> 2;
        int r    = nt * 256 + nb * 8 + ncol;
        int k0   = kt * 16 + (lane & 3) * 2;
        __half w4[4];
#pragma unroll
        for (int q = 0; q < 4; q++) {
            int k = k0 + (q >> 1) * 8 + (q & 1);   // k0,k0+1,k0+8,k0+9
            float w;
            if (l == 0)       w = Whh[(size_t)r * H + k];
            else if (k < H)   w = Wihr[(size_t)((l - 1) * G4 + r) * H + k];
            else              w = Whh[(size_t)(l * G4 + r) * H + (k - H)];
            w4[q] = __float2half(w);
        }
        g_Wp[idx] = make_uint2(pk(w4[0], w4[1]), pk(w4[2], w4[3]));
    } else {
        int j = idx - 4 * 32 * 32 * 4 * 32;
        if (j < 4096) {
            int l = j >> 10, nb = (j >> 5) & 31, nl = j & 31;
            int r = (nl >> 3) * 256 + nb * 8 + (nl & 7);
            g_bias[j] = bih[l * G4 + r] + bhh[l * G4 + r];
        } else if (j < 4096 + 10240) {
            int jj = j - 4096;
            int nb = jj / 320, rem = jj % 320, nl = rem / 10, e = rem % 10;
            int r = (nl >> 3) * 256 + nb * 8 + (nl & 7);
            g_w0p[jj] = Wih0[r * E + e];
        }
    }
}

// ---------------- prep 2: s = relu((e01[x]+p01) @ f01_w.T + f01_b) ----------------
__global__ void k_embed(const int* __restrict__ x, const float* __restrict__ e01,
                        const float* __restrict__ p01, const float* __restrict__ f01w,
                        const float* __restrict__ f01b) {
    int idx = blockIdx.x * 256 + threadIdx.x;
    if (idx >= S * B) return;
    int t = idx / B;
    int tok = x[idx];
    float v[E];
#pragma unroll
    for (int e = 0; e < E; e++) v[e] = e01[tok * E + e] + p01[t * E + e];
    float* so = g_S + (size_t)idx * E;
#pragma unroll
    for (int i = 0; i < E; i++) {
        float a = f01b[i];
#pragma unroll
        for (int e = 0; e < E; e++) a += v[e] * f01w[i * E + e];
        so[i] = fmaxf(a, 0.0f);
    }
}

// ---------------- prep 3: ssum + h0/c0 + counter reset (fused) ----------------
__global__ void k_ssum_init(const float* __restrict__ f02w, const float* __restrict__ f02b,
                            const float* __restrict__ f03w, const float* __restrict__ f03b) {
    __shared__ float red[256 * E];
    __shared__ float ss[E];
    int b = blockIdx.x, tid = threadIdx.x;
    float acc[E];
#pragma unroll
    for (int e = 0; e < E; e++) acc[e] = 0.0f;
    for (int t = tid; t < S; t += 256) {
        const float* sp = g_S + ((size_t)t * B + b) * E;
#pragma unroll
        for (int e = 0; e < E; e++) acc[e] += sp[e];
    }
#pragma unroll
    for (int e = 0; e < E; e++) red[tid * E + e] = acc[e];
    __syncthreads();
    for (int s = 128; s > 0; s >>= 1) {
        if (tid < s) {
#pragma unroll
            for (int e = 0; e < E; e++) red[tid * E + e] += red[(tid + s) * E + e];
        }
        __syncthreads();
    }
    if (tid < E) ss[tid] = red[tid];
    if (b == 0 && tid < L * 8) g_cnt[tid] = 0;
    __syncthreads();
    __half* Hb = (__half*)g_Hq;
#pragma unroll
    for (int i = 0; i < 4; i++) {
        int r = tid + i * 256;           // gate row 0..1023
        float ah = f02b[r], ac = f03b[r];
#pragma unroll
        for (int e = 0; e < E; e++) {
            ah += ss[e] * f02w[r * E + e];
            ac += ss[e] * f03w[r * E + e];
        }
        ah = fmaxf(ah, 0.0f);
        ac = fmaxf(ac, 0.0f);
        int l = r >> 8, j = r & 255;
        int u = unitj(j & ~1);
        // initial h = "step -1" output -> slot 2
        size_t base = (((size_t)(l * 3 + 2) * B) + b) * 512 + u * 4 + (j & 1);
        __half hh = __float2half(ah);
        Hb[base]     = hh;
        Hb[base + 2] = __float2half(ah - __half2float(hh));
        g_C0[((size_t)l * B + b) * H + j] = ac;
    }
}

// ---------------- persistent recurrent kernel: per-warp decoupled pipeline ----------------
__global__ void __launch_bounds__(256, 1) lstm_rec(float* __restrict__ out) {
    const int bid = blockIdx.x;
    const int l   = bid >> 5;
    const int nb  = bid & 31;
    const int tid = threadIdx.x;
    const int warp = tid >> 5;
    const int lane = tid & 31;

    extern __shared__ unsigned char smem[];
    uint2* Wsm  = (uint2*)smem;                 // [32][4][32] uint2 = 32KB
    float* bsm  = (float*)(Wsm + 4096);         // 32
    float* w0sm = bsm + 32;                     // 320 (layer 0 only)

    const int Kkt = (l == 0) ? 16 : 32;
    {
        const uint2* src = g_Wp + (size_t)(l * 32 + nb) * 4096;
        for (int i = tid; i < Kkt * 128; i += 256) Wsm[i] = src[i];
        if (tid < 32) bsm[tid] = g_bias[(l * 32 + nb) * 32 + tid];
        if (l == 0) for (int i = tid; i < 320; i += 256) w0sm[i] = g_w0p[nb * 320 + i];
    }

    const int qd  = lane & 3;
    const int r0  = lane >> 2;
    const int c2  = qd * 2;
    const int b0  = warp * 16 + r0;
    const int jj0 = nb * 8 + c2;
    const int ust = unitj(jj0);                 // store unit within row

    float cst[4];
    cst[0] = g_C0[((size_t)l * B + b0) * H + jj0];
    cst[1] = g_C0[((size_t)l * B + b0) * H + jj0 + 1];
    cst[2] = g_C0[((size_t)l * B + b0 + 8) * H + jj0];
    cst[3] = g_C0[((size_t)l * B + b0 + 8) * H + jj0 + 1];
    __syncthreads();

    // per-lane smem weight pointers
    const uint2* WqIn  = Wsm + lane;                       // input half (l>0): kt 0..15
    const uint2* WqOwn = Wsm + (l ? 16 * 128 : 0) + lane;  // Whh half

    int* cOwn = &g_cnt[l * 8 + warp];
    int* cIn  = (l > 0) ? &g_cnt[(l - 1) * 8 + warp] : nullptr;
    int* cDn  = (l < 3) ? &g_cnt[(l + 1) * 8 + warp] : nullptr;

    // slot bases (uint4 index): slot s of layer l at (l*3+s)*B*64
    const size_t laneOfs = (size_t)b0 * 64 + qd;
    int scur = 0, sprev = 2;

    float bias_r[4][2];
#pragma unroll
    for (int nt = 0; nt < 4; nt++) {
        bias_r[nt][0] = bsm[nt * 8 + c2];
        bias_r[nt][1] = bsm[nt * 8 + c2 + 1];
    }

    for (int t = 0; t < S; ++t) {
        float acc[4][4];
#pragma unroll
        for (int nt = 0; nt < 4; nt++) {
#pragma unroll
            for (int rg = 0; rg < 4; rg++)
                acc[nt][rg] = bias_r[nt][rg & 1];
        }

        if (l == 0) {  // E=10 input contribution (independent of all counters)
            float sv0[E], sv1[E];
            const float* sp = g_S + ((size_t)t * B + b0) * E;
#pragma unroll
            for (int e = 0; e < E; e++) { sv0[e] = sp[e]; sv1[e] = sp[8 * E + e]; }
#pragma unroll
            for (int nt = 0; nt < 4; nt++) {
                const float* wA = w0sm + (nt * 8 + c2) * E;
                const float* wB = wA + E;
#pragma unroll
                for (int e = 0; e < E; e++) {
                    acc[nt][0] += sv0[e] * wA[e];
                    acc[nt][1] += sv0[e] * wB[e];
                    acc[nt][2] += sv1[e] * wA[e];
                    acc[nt][3] += sv1[e] * wB[e];
                }
            }
        }

        // wait: own layer step t-1 done by all 32 blocks (warp lane-uniform poll)
        if (t > 0) while (ld_acq(cOwn) < 32 * t) { }

        // Whh half (own h from step t-1, slot sprev)
        do_half(g_Hq + (size_t)(l * 3 + sprev) * B * 64 + laneOfs, WqOwn, acc);

        // input half (layer l-1 h from step t, slot scur)
        if (l > 0) {
            while (ld_acq(cIn) < 32 * (t + 1)) { }
            do_half(g_Hq + (size_t)((l - 1) * 3 + scur) * B * 64 + laneOfs, WqIn, acc);
        }

        // epilogue
        float hv[4];
#pragma unroll
        for (int rg = 0; rg < 4; rg++) {
            float iv = fsig(acc[0][rg]);
            float fv = fsig(acc[1][rg]);
            float gv = ftanh(acc[2][rg]);
            float ov = fsig(acc[3][rg]);
            float cv = fv * cst[rg] + iv * gv;
            cst[rg] = cv;
            hv[rg] = ov * ftanh(cv);
        }

        // anti-overwrite: layer above consumed h[t-3] (only gates the store)
        if (l < 3 && t >= 3) while (ld_acq(cDn) < 32 * (t - 2)) { }

        unsigned long long* Ow =
            (unsigned long long*)(g_Hq + (size_t)(l * 3 + scur) * B * 64);
#pragma unroll
        for (int half = 0; half < 2; half++) {
            float h0v = hv[half * 2], h1v = hv[half * 2 + 1];
            int row = b0 + half * 8;
            __half hh0 = __float2half(h0v);
            __half hh1 = __float2half(h1v);
            unsigned lo32 = pk(hh0, hh1);
            unsigned hi32 = pk(__float2half(h0v - __half2float(hh0)),
                               __float2half(h1v - __half2float(hh1)));
            unsigned long long val = (unsigned long long)lo32 |
                                     ((unsigned long long)hi32 << 32);
            Ow[(size_t)row * 128 + ust] = val;
            if (t == S - 1) {
                float2 o2 = make_float2(h0v, h1v);
                *(float2*)(out + (size_t)row * G4 + l * H + jj0) = o2;
            }
        }

        __syncwarp();
        if (lane == 0) red_rel(cOwn, 1);

        sprev = scur;
        scur = (scur == 2) ? 0 : scur + 1;
    }
}

// ---------------- launch ----------------
extern "C" void kernel_launch(void* const* d_in, const int* in_sizes, int n_in,
                              void* d_out, int out_size) {
    const int*   x    = (const int*)d_in[0];
    const float* e01  = (const float*)d_in[1];
    const float* p01  = (const float*)d_in[2];
    const float* f01w = (const float*)d_in[3];
    const float* f01b = (const float*)d_in[4];
    const float* f02w = (const float*)d_in[5];
    const float* f02b = (const float*)d_in[6];
    const float* f03w = (const float*)d_in[7];
    const float* f03b = (const float*)d_in[8];
    const float* Wih0 = (const float*)d_in[9];
    const float* Wihr = (const float*)d_in[10];
    const float* Whh  = (const float*)d_in[11];
    const float* bih  = (const float*)d_in[12];
    const float* bhh  = (const float*)d_in[13];
    float* out = (float*)d_out;

    k_prep<<<(4 * 32 * 32 * 4 * 32 + 4096 + 10240 + 255) / 256, 256>>>(Wih0, Wihr, Whh, bih, bhh);
    k_embed<<<(S * B + 255) / 256, 256>>>(x, e01, p01, f01w, f01b);
    k_ssum_init<<<B, 256>>>(f02w, f02b, f03w, f03b);

    const int smem_bytes = 4096 * 8 + (32 + 320) * 4;  // ~34KB
    cudaFuncSetAttribute(lstm_rec, cudaFuncAttributeMaxDynamicSharedMemorySize,
                         smem_bytes);
    lstm_rec<<<NBLK, 256, smem_bytes>>>(out);
}